// round 14
// baseline (speedup 1.0000x reference)
#include <cuda_runtime.h>
#include <cuda_bf16.h>
#include <math.h>

#define T_FRAMES 2000
#define NB 4
#define NHARM 6
#define T_AUD 960000
#define GRP 128
#define NG 7500                  // 128-sample groups per batch
#define NGTOT 30000
#define SCALE_POS (2000.0f/960000.0f)
#define INV_SR (1.0f/48000.0f)
#define TWO_PI_F 6.2831853071795864769f

#define NBLOCKS 296              // 2 per SM x 148: single wave, all resident
#define NTHREADS 512
#define NWARPS_G (NBLOCKS * 16)  // 4736
#define CONV_NB 252              // one 32-frame tile per block
#define NG_PART 682              // ceil(7500/11)
#define W1_ELEMS (32 * 129 * 5)  // 20640

// ---------------- scratch ----------------
__device__ float  g_amp[NB * T_FRAMES * 8];  // [b][t][8], ch 0..5 valid
__device__ float4 g_w4[129 * 32];            // w1 k=0..3, [ic][c]
__device__ float  g_w1s[129 * 32];           // w1 k=4,    [ic][c]
__device__ float  g_tot[NB * NG];
__device__ float  g_carry[NB * NG];
__device__ float  g_consts[16];              // [0..5]=A, [6..11]=B
__device__ unsigned g_cnt;                   // grid barrier counter (returns to 0)
__device__ volatile unsigned g_sense;        // grid barrier sense (returns to 0)
__device__ unsigned g_cnt_b[NB];             // per-batch totals-done counters (reset by scanner)

__device__ __forceinline__ float tanh_approx(float x) {
    float y;
    asm("tanh.approx.f32 %0, %1;" : "=f"(y) : "f"(x));
    return y;
}

__device__ __forceinline__ void grid_barrier(unsigned target) {
    __syncthreads();
    if (threadIdx.x == 0) {
        __threadfence();
        unsigned old = atomicAdd(&g_cnt, 1u);
        if (old == NBLOCKS - 1) {
            *(volatile unsigned*)&g_cnt = 0u;
            __threadfence();
            g_sense = target;
        } else {
            while (g_sense != target) __nanosleep(32);
            __threadfence();
        }
    }
    __syncthreads();
}

__global__ void __launch_bounds__(NTHREADS, 2) fused_kernel(
    const float* __restrict__ f0, const float* __restrict__ mel,
    const float* __restrict__ noise,
    const float* __restrict__ w1, const float* __restrict__ b1,
    const float* __restrict__ w2, const float* __restrict__ b2,
    const float* __restrict__ als, const float* __restrict__ pho,
    const float* __restrict__ lnv, const float* __restrict__ lnu,
    float* __restrict__ out)
{
    __shared__ float  sxx[129 * 36];
    __shared__ float  sh[32 * 32];
    __shared__ double wsum[16];
    __shared__ int    s_do_scan;

    const int bid  = blockIdx.x;
    const int tid  = threadIdx.x;
    const int wid  = tid >> 5;
    const int lane = tid & 31;
    const unsigned FULL = 0xffffffffu;

    // ================= PHASE 0: weight transpose + consts (tiny) =================
    if (bid < 41) {
        int e = bid * NTHREADS + tid;
        if (e < W1_ELEMS) {
            int c  = e / 645;
            int r  = e - c * 645;
            int ic = r / 5;
            int k  = r - ic * 5;
            float val = w1[e];
            if (k < 4) ((float*)g_w4)[(ic * 32 + c) * 4 + k] = val;
            else       g_w1s[ic * 32 + c] = val;
        }
    }
    if (bid == 100 && tid < NHARM) {
        float e  = expf(als[tid]);
        float ph = TWO_PI_F * pho[tid];
        g_consts[tid]     = e * cosf(ph);
        g_consts[6 + tid] = e * sinf(ph);
    }

    grid_barrier(1u);

    // ================= PHASE A: conv (252) || totals+noise+scan (44) =================
    if (bid < CONV_NB) {
        const int b  = bid / 63;
        const int t0 = (bid - b * 63) * 32;

        for (int e = tid; e < 129 * 36; e += NTHREADS) {
            int ic = e / 36, tt = e - ic * 36;
            int t = t0 + tt - 2;
            float v = 0.0f;
            if (t >= 0 && t < T_FRAMES)
                v = (ic == 0) ? f0[b * T_FRAMES + t]
                              : mel[(b * 128 + (ic - 1)) * T_FRAMES + t];
            sxx[e] = v;
        }
        __syncthreads();

        const int c  = tid & 31;            // channel = lane -> coalesced weight LDG
        const int tb = (tid >> 5) * 2;      // frames tb, tb+1 (warp-uniform)

        float acc0, acc1;
        acc0 = acc1 = b1[c];

#pragma unroll 4
        for (int ic = 0; ic < 129; ic++) {
            float4 wa = __ldg(&g_w4[ic * 32 + c]);
            float  w4 = __ldg(&g_w1s[ic * 32 + c]);
            float2 xa = *(const float2*)&sxx[ic * 36 + tb];
            float2 xb = *(const float2*)&sxx[ic * 36 + tb + 2];
            float2 xc = *(const float2*)&sxx[ic * 36 + tb + 4];
            acc0 = fmaf(wa.x, xa.x, acc0); acc0 = fmaf(wa.y, xa.y, acc0);
            acc0 = fmaf(wa.z, xb.x, acc0); acc0 = fmaf(wa.w, xb.y, acc0);
            acc0 = fmaf(w4,  xc.x, acc0);
            acc1 = fmaf(wa.x, xa.y, acc1); acc1 = fmaf(wa.y, xb.x, acc1);
            acc1 = fmaf(wa.z, xb.y, acc1); acc1 = fmaf(wa.w, xc.x, acc1);
            acc1 = fmaf(w4,  xc.y, acc1);
        }
        sh[c * 32 + tb + 0] = acc0 / (1.0f + __expf(-acc0));
        sh[c * 32 + tb + 1] = acc1 / (1.0f + __expf(-acc1));
        __syncthreads();

        if (tid < NHARM * 32) {
            int nh = tid >> 5, tl = tid & 31;
            int t = t0 + tl;
            if (t < T_FRAMES) {
                float s = b2[nh];
                const float* wp = &w2[nh * 32];
#pragma unroll
                for (int cc = 0; cc < 32; cc++)
                    s = fmaf(__ldg(wp + cc), sh[cc * 32 + tl], s);
                g_amp[((size_t)b * T_FRAMES + t) * 8 + nh] = s;
            }
        }
    } else {
        // ---- totals role: 44 blocks, 11 per batch ----
        const int r = bid - CONV_NB;        // 0..43
        const int b = r / 11;
        const int p = r - b * 11;

        const float nvs = __expf(lnv[0]);
        const float nus = __expf(lnu[0]);
        const int g_lo = p * NG_PART;
        const int g_hi = min(g_lo + NG_PART, NG);
        const float* f0b = f0 + b * T_FRAMES;

        for (int g = g_lo + wid; g < g_hi; g += 16) {
            int base = g * GRP + lane * 4;
            float4 nz = *(const float4*)(noise + (size_t)b * T_AUD + base);
            const float* nzp = &nz.x;
            float o4[4];
            float s = 0.0f;
#pragma unroll
            for (int j = 0; j < 4; j++) {
                int i = base + j;
                float pos = fmaf((float)i + 0.5f, SCALE_POS, -0.5f);
                pos = fminf(fmaxf(pos, 0.0f), 1999.0f);
                int i0 = (int)pos;
                int i1 = min(i0 + 1, 1999);
                float w = pos - (float)i0;
                float v = f0b[i0] * (1.0f - w) + f0b[i1] * w;
                s += v * INV_SR;
                o4[j] = nzp[j] * ((v > 1.0f) ? nvs : nus);
            }
            *(float4*)(out + (size_t)(b * 7 + 6) * T_AUD + base) =
                make_float4(o4[0], o4[1], o4[2], o4[3]);
#pragma unroll
            for (int off = 16; off; off >>= 1)
                s += __shfl_down_sync(FULL, s, off);
            if (lane == 0) g_tot[b * NG + g] = s;
        }

        // last finisher of this batch runs the batch's scan (bounded, no spin)
        __syncthreads();
        if (tid == 0) {
            __threadfence();
            unsigned done = atomicAdd(&g_cnt_b[b], 1u);
            s_do_scan = (done == 10u);
            if (done == 10u) { g_cnt_b[b] = 0u; }
        }
        __syncthreads();
        if (s_do_scan) {
            __threadfence();
            const int PER = 15;             // 512*15 >= 7500
            const int s0 = tid * PER;
            float tl[PER];
            double loc = 0.0;
#pragma unroll
            for (int j = 0; j < PER; j++) {
                int idx = s0 + j;
                float t = (idx < NG) ? g_tot[b * NG + idx] : 0.0f;
                tl[j] = t;
                loc += (double)t;
            }
            double v = loc;
#pragma unroll
            for (int off = 1; off < 32; off <<= 1) {
                double n = __shfl_up_sync(FULL, v, off);
                if (lane >= off) v += n;
            }
            if (lane == 31) wsum[wid] = v;
            __syncthreads();
            if (wid == 0 && lane < 16) {
                double x = wsum[lane];
#pragma unroll
                for (int off = 1; off < 16; off <<= 1) {
                    double n = __shfl_up_sync(0xffffu, x, off);
                    if (lane >= off) x += n;
                }
                wsum[lane] = x;
            }
            __syncthreads();
            double base = (v - loc) + (wid ? wsum[wid - 1] : 0.0);
#pragma unroll
            for (int j = 0; j < PER; j++) {
                int idx = s0 + j;
                if (idx < NG)
                    g_carry[b * NG + idx] = (float)(base - floor(base));
                base += (double)tl[j];
            }
        }
    }

    grid_barrier(0u);

    // ================= PHASE B: harmonic synthesis (channels 0..5) =================
    float cA[6], cB[6];
#pragma unroll
    for (int h = 0; h < 6; h++) { cA[h] = g_consts[h]; cB[h] = g_consts[6 + h]; }

    for (int gg = bid * 16 + wid; gg < NGTOT; gg += NWARPS_G) {
        const int b    = gg / NG;
        const int g    = gg - b * NG;
        const int base = g * GRP;
        const float* f0b = f0 + b * T_FRAMES;

        // warp-uniform rows F, F+1, F+2 (a 128-sample group spans < 0.27 frame)
        float pstart = fmaxf(fmaf((float)base + 0.5f, SCALE_POS, -0.5f), 0.0f);
        const int F  = (int)pstart;
        const int F1 = min(F + 1, 1999);
        const int F2 = min(F + 2, 1999);

        const float* rp = g_amp + ((size_t)b * T_FRAMES + F) * 8;
        float4 a4 = __ldg((const float4*)rp);
        float2 a2 = __ldg((const float2*)(rp + 4));
        const float* rq = g_amp + ((size_t)b * T_FRAMES + F1) * 8;
        float4 b4 = __ldg((const float4*)rq);
        float2 b2v = __ldg((const float2*)(rq + 4));
        const float* rr = g_amp + ((size_t)b * T_FRAMES + F2) * 8;
        float4 c4 = __ldg((const float4*)rr);
        float2 c2 = __ldg((const float2*)(rr + 4));
        float rA[6] = {a4.x, a4.y, a4.z, a4.w, a2.x, a2.y};
        float rB[6] = {b4.x, b4.y, b4.z, b4.w, b2v.x, b2v.y};
        float rC[6] = {c4.x, c4.y, c4.z, c4.w, c2.x, c2.y};
        const float f0A = __ldg(f0b + F);
        const float f0B = __ldg(f0b + F1);
        const float f0C = __ldg(f0b + F2);

        const int si = base + lane * 4;
        float inc[4], voiced[4], wf[4];
        unsigned dmask = 0;
#pragma unroll
        for (int j = 0; j < 4; j++) {
            float pos = fmaf((float)(si + j) + 0.5f, SCALE_POS, -0.5f);
            pos = fminf(fmaxf(pos, 0.0f), 1999.0f);
            int i0 = (int)pos;
            float w = pos - (float)i0;
            int d = i0 - F;                     // 0 or 1
            dmask |= (unsigned)d << j;
            wf[j] = w;
            float fa = d ? f0B : f0A;
            float fb = d ? f0C : f0B;
            float fv = fa * (1.0f - w) + fb * w;
            voiced[j] = (fv > 1.0f) ? 1.0f : 0.0f;
            inc[j] = fv * INV_SR;
        }

        float inc4 = ((inc[0] + inc[1]) + inc[2]) + inc[3];
        float sv = inc4;
#pragma unroll
        for (int off = 1; off < 32; off <<= 1) {
            float n = __shfl_up_sync(FULL, sv, off);
            if (lane >= off) sv += n;
        }
        float running = g_carry[b * NG + g] + (sv - inc4);

        float s1[4], c1[4], sk[4], ck[4];
#pragma unroll
        for (int j = 0; j < 4; j++) {
            running += inc[j];
            __sincosf(TWO_PI_F * running, &s1[j], &c1[j]);
            sk[j] = s1[j]; ck[j] = c1[j];
        }

        float* op = out + (size_t)(b * 7) * T_AUD + si;
#pragma unroll
        for (int h = 0; h < 6; h++) {
            if (h) {
#pragma unroll
                for (int j = 0; j < 4; j++) {
                    float t = sk[j] * c1[j] + ck[j] * s1[j];
                    ck[j] = ck[j] * c1[j] - sk[j] * s1[j];
                    sk[j] = t;
                }
            }
            float o4[4];
#pragma unroll
            for (int j = 0; j < 4; j++) {
                int d = (dmask >> j) & 1;
                float a0 = d ? rB[h] : rA[h];
                float a1 = d ? rC[h] : rB[h];
                float am = a0 * (1.0f - wf[j]) + a1 * wf[j];
                float sig2 = 1.0f + tanh_approx(0.5f * am);
                o4[j] = (sk[j] * cA[h] + ck[j] * cB[h]) * (sig2 * voiced[j]);
            }
            *(float4*)(op + (size_t)h * T_AUD) =
                make_float4(o4[0], o4[1], o4[2], o4[3]);
        }
    }
}

// ---------------- launcher ----------------
extern "C" void kernel_launch(void* const* d_in, const int* in_sizes, int n_in,
                              void* d_out, int out_size)
{
    const float* f0    = (const float*)d_in[0];
    const float* mel   = (const float*)d_in[1];
    const float* noise = (const float*)d_in[2];
    const float* w1    = (const float*)d_in[3];
    const float* b1    = (const float*)d_in[4];
    const float* w2    = (const float*)d_in[5];
    const float* b2    = (const float*)d_in[6];
    const float* als   = (const float*)d_in[7];
    const float* pho   = (const float*)d_in[8];
    const float* lnv   = (const float*)d_in[9];
    const float* lnu   = (const float*)d_in[10];
    float* out = (float*)d_out;

    fused_kernel<<<NBLOCKS, NTHREADS>>>(f0, mel, noise, w1, b1, w2, b2,
                                        als, pho, lnv, lnu, out);
}

// round 15
// speedup vs baseline: 1.3832x; 1.3832x over previous
#include <cuda_runtime.h>
#include <cuda_bf16.h>
#include <math.h>

#define T_FRAMES 2000
#define NB 4
#define NHARM 6
#define T_AUD 960000
#define GRP 128
#define NG 7500                  // 128-sample groups per batch
#define NGTOT 30000
#define SCALE_POS (2000.0f/960000.0f)
#define INV_SR (1.0f/48000.0f)
#define TWO_PI_F 6.2831853071795864769f

#define NBLOCKS 296              // 2 per SM x 148: single wave, all resident
#define NTHREADS 512
#define NWARPS_G (NBLOCKS * 16)  // 4736
#define CONV_NB 252              // one 32-frame tile per block
#define W1_ELEMS (32 * 129 * 5)  // 20640

// ---------------- scratch ----------------
__device__ float  g_amp[NB * T_FRAMES * 8];  // [b][t][8], ch 0..5 valid
__device__ float4 g_w4[129 * 32];            // w1 k=0..3, [ic][c]
__device__ float  g_w1s[129 * 32];           // w1 k=4,    [ic][c]
__device__ float  g_tot[NB * NG];
__device__ float  g_carry[NB * NG];
__device__ float  g_consts[16];              // [0..5]=A, [6..11]=B
__device__ unsigned g_cnt;                   // barrier counter (returns to 0)
__device__ volatile unsigned g_sense;        // barrier sense (returns to 0)

__device__ __forceinline__ float tanh_approx(float x) {
    float y;
    asm("tanh.approx.f32 %0, %1;" : "=f"(y) : "f"(x));
    return y;
}

__device__ __forceinline__ void grid_barrier(unsigned target) {
    __syncthreads();
    if (threadIdx.x == 0) {
        __threadfence();
        unsigned old = atomicAdd(&g_cnt, 1u);
        if (old == NBLOCKS - 1) {
            *(volatile unsigned*)&g_cnt = 0u;
            __threadfence();
            g_sense = target;
        } else {
            while (g_sense != target) __nanosleep(32);
            __threadfence();
        }
    }
    __syncthreads();
}

__global__ void __launch_bounds__(NTHREADS, 2) fused_kernel(
    const float* __restrict__ f0, const float* __restrict__ mel,
    const float* __restrict__ noise,
    const float* __restrict__ w1, const float* __restrict__ b1,
    const float* __restrict__ w2, const float* __restrict__ b2,
    const float* __restrict__ als, const float* __restrict__ pho,
    const float* __restrict__ lnv, const float* __restrict__ lnu,
    float* __restrict__ out)
{
    __shared__ float  sxx[129 * 36];
    __shared__ float  sh[32 * 32];
    __shared__ double wsum[16];

    const int bid  = blockIdx.x;
    const int tid  = threadIdx.x;
    const int wid  = tid >> 5;
    const int lane = tid & 31;
    const unsigned FULL = 0xffffffffu;

    // ================= PHASE 1: totals + noise channel + transpose + consts ========
    if (bid < 41) {
        int e = bid * NTHREADS + tid;
        if (e < W1_ELEMS) {
            int c  = e / 645;
            int r  = e - c * 645;
            int ic = r / 5;
            int k  = r - ic * 5;
            float val = w1[e];
            if (k < 4) ((float*)g_w4)[(ic * 32 + c) * 4 + k] = val;
            else       g_w1s[ic * 32 + c] = val;
        }
    }
    if (bid == 100 && tid < NHARM) {
        float e  = expf(als[tid]);
        float ph = TWO_PI_F * pho[tid];
        g_consts[tid]     = e * cosf(ph);
        g_consts[6 + tid] = e * sinf(ph);
    }
    {
        const float nvs = __expf(lnv[0]);
        const float nus = __expf(lnu[0]);
        for (int gg = bid * 16 + wid; gg < NGTOT; gg += NWARPS_G) {
            int b = gg / NG;
            int g = gg - b * NG;
            const float* f0b = f0 + b * T_FRAMES;
            int base = g * GRP + lane * 4;
            float4 nz = *(const float4*)(noise + (size_t)b * T_AUD + base);
            const float* nzp = &nz.x;
            float o4[4];
            float s = 0.0f;
#pragma unroll
            for (int j = 0; j < 4; j++) {
                int i = base + j;
                float pos = fmaf((float)i + 0.5f, SCALE_POS, -0.5f);
                pos = fminf(fmaxf(pos, 0.0f), 1999.0f);
                int i0 = (int)pos;
                int i1 = min(i0 + 1, 1999);
                float w = pos - (float)i0;
                float v = f0b[i0] * (1.0f - w) + f0b[i1] * w;
                s += v * INV_SR;
                o4[j] = nzp[j] * ((v > 1.0f) ? nvs : nus);
            }
            *(float4*)(out + (size_t)(b * 7 + 6) * T_AUD + base) =
                make_float4(o4[0], o4[1], o4[2], o4[3]);
#pragma unroll
            for (int off = 16; off; off >>= 1)
                s += __shfl_down_sync(FULL, s, off);
            if (lane == 0) g_tot[b * NG + g] = s;
        }
    }

    grid_barrier(1u);

    // ================= PHASE 2: conv (252 blocks, 1 tile each) || scan (4 blocks) ==
    if (bid < CONV_NB) {
        const int b  = bid / 63;
        const int t0 = (bid - b * 63) * 32;

        for (int e = tid; e < 129 * 36; e += NTHREADS) {
            int ic = e / 36, tt = e - ic * 36;
            int t = t0 + tt - 2;
            float v = 0.0f;
            if (t >= 0 && t < T_FRAMES)
                v = (ic == 0) ? f0[b * T_FRAMES + t]
                              : mel[(b * 128 + (ic - 1)) * T_FRAMES + t];
            sxx[e] = v;
        }
        __syncthreads();

        const int c  = tid & 31;            // channel = lane -> coalesced weight LDG
        const int tb = (tid >> 5) * 2;      // frames tb, tb+1 (warp-uniform)

        float acc0, acc1;
        acc0 = acc1 = b1[c];

#pragma unroll 4
        for (int ic = 0; ic < 129; ic++) {
            float4 wa = __ldg(&g_w4[ic * 32 + c]);
            float  w4 = __ldg(&g_w1s[ic * 32 + c]);
            float2 xa = *(const float2*)&sxx[ic * 36 + tb];
            float2 xb = *(const float2*)&sxx[ic * 36 + tb + 2];
            float2 xc = *(const float2*)&sxx[ic * 36 + tb + 4];
            acc0 = fmaf(wa.x, xa.x, acc0); acc0 = fmaf(wa.y, xa.y, acc0);
            acc0 = fmaf(wa.z, xb.x, acc0); acc0 = fmaf(wa.w, xb.y, acc0);
            acc0 = fmaf(w4,  xc.x, acc0);
            acc1 = fmaf(wa.x, xa.y, acc1); acc1 = fmaf(wa.y, xb.x, acc1);
            acc1 = fmaf(wa.z, xb.y, acc1); acc1 = fmaf(wa.w, xc.x, acc1);
            acc1 = fmaf(w4,  xc.y, acc1);
        }
        sh[c * 32 + tb + 0] = acc0 / (1.0f + __expf(-acc0));
        sh[c * 32 + tb + 1] = acc1 / (1.0f + __expf(-acc1));
        __syncthreads();

        if (tid < NHARM * 32) {
            int nh = tid >> 5, tl = tid & 31;
            int t = t0 + tl;
            if (t < T_FRAMES) {
                float s = b2[nh];
                const float* wp = &w2[nh * 32];
#pragma unroll
                for (int cc = 0; cc < 32; cc++)
                    s = fmaf(__ldg(wp + cc), sh[cc * 32 + tl], s);
                g_amp[((size_t)b * T_FRAMES + t) * 8 + nh] = s;
            }
        }
    } else if (bid < CONV_NB + NB) {
        // ---- scan role: one block per batch, 512 threads, PER=15 ----
        const int b = bid - CONV_NB;
        const int PER = 15;                 // 512*15 >= 7500
        const int s0 = tid * PER;
        float tl[PER];
        double loc = 0.0;
#pragma unroll
        for (int j = 0; j < PER; j++) {
            int idx = s0 + j;
            float t = (idx < NG) ? g_tot[b * NG + idx] : 0.0f;
            tl[j] = t;
            loc += (double)t;
        }
        double v = loc;
#pragma unroll
        for (int off = 1; off < 32; off <<= 1) {
            double n = __shfl_up_sync(FULL, v, off);
            if (lane >= off) v += n;
        }
        if (lane == 31) wsum[wid] = v;
        __syncthreads();
        if (wid == 0 && lane < 16) {
            double x = wsum[lane];
#pragma unroll
            for (int off = 1; off < 16; off <<= 1) {
                double n = __shfl_up_sync(0xffffu, x, off);
                if (lane >= off) x += n;
            }
            wsum[lane] = x;
        }
        __syncthreads();
        double base = (v - loc) + (wid ? wsum[wid - 1] : 0.0);
#pragma unroll
        for (int j = 0; j < PER; j++) {
            int idx = s0 + j;
            if (idx < NG)
                g_carry[b * NG + idx] = (float)(base - floor(base));
            base += (double)tl[j];
        }
    }

    grid_barrier(0u);

    // ================= PHASE 3: harmonic synthesis (channels 0..5) =================
    float cA[6], cB[6];
#pragma unroll
    for (int h = 0; h < 6; h++) { cA[h] = g_consts[h]; cB[h] = g_consts[6 + h]; }

    for (int gg = bid * 16 + wid; gg < NGTOT; gg += NWARPS_G) {
        const int b    = gg / NG;
        const int g    = gg - b * NG;
        const int base = g * GRP;
        const float* f0b = f0 + b * T_FRAMES;

        // warp-uniform rows F, F+1, F+2 (a 128-sample group spans < 0.27 frame)
        float pstart = fmaxf(fmaf((float)base + 0.5f, SCALE_POS, -0.5f), 0.0f);
        const int F  = (int)pstart;
        const int F1 = min(F + 1, 1999);
        const int F2 = min(F + 2, 1999);

        const float* rp = g_amp + ((size_t)b * T_FRAMES + F) * 8;
        float4 a4 = __ldg((const float4*)rp);
        float2 a2 = __ldg((const float2*)(rp + 4));
        const float* rq = g_amp + ((size_t)b * T_FRAMES + F1) * 8;
        float4 b4 = __ldg((const float4*)rq);
        float2 b2v = __ldg((const float2*)(rq + 4));
        const float* rr = g_amp + ((size_t)b * T_FRAMES + F2) * 8;
        float4 c4 = __ldg((const float4*)rr);
        float2 c2 = __ldg((const float2*)(rr + 4));
        float rA[6] = {a4.x, a4.y, a4.z, a4.w, a2.x, a2.y};
        float rB[6] = {b4.x, b4.y, b4.z, b4.w, b2v.x, b2v.y};
        float rC[6] = {c4.x, c4.y, c4.z, c4.w, c2.x, c2.y};
        const float f0A = __ldg(f0b + F);
        const float f0B = __ldg(f0b + F1);
        const float f0C = __ldg(f0b + F2);

        const int si = base + lane * 4;
        float inc[4], voiced[4], wf[4];
        unsigned dmask = 0;
#pragma unroll
        for (int j = 0; j < 4; j++) {
            float pos = fmaf((float)(si + j) + 0.5f, SCALE_POS, -0.5f);
            pos = fminf(fmaxf(pos, 0.0f), 1999.0f);
            int i0 = (int)pos;
            float w = pos - (float)i0;
            int d = i0 - F;                     // 0 or 1
            dmask |= (unsigned)d << j;
            wf[j] = w;
            float fa = d ? f0B : f0A;
            float fb = d ? f0C : f0B;
            float fv = fa * (1.0f - w) + fb * w;
            voiced[j] = (fv > 1.0f) ? 1.0f : 0.0f;
            inc[j] = fv * INV_SR;
        }

        float inc4 = ((inc[0] + inc[1]) + inc[2]) + inc[3];
        float sv = inc4;
#pragma unroll
        for (int off = 1; off < 32; off <<= 1) {
            float n = __shfl_up_sync(FULL, sv, off);
            if (lane >= off) sv += n;
        }
        float running = g_carry[b * NG + g] + (sv - inc4);

        float s1[4], c1[4], sk[4], ck[4];
#pragma unroll
        for (int j = 0; j < 4; j++) {
            running += inc[j];
            __sincosf(TWO_PI_F * running, &s1[j], &c1[j]);
            sk[j] = s1[j]; ck[j] = c1[j];
        }

        float* op = out + (size_t)(b * 7) * T_AUD + si;
#pragma unroll
        for (int h = 0; h < 6; h++) {
            if (h) {
#pragma unroll
                for (int j = 0; j < 4; j++) {
                    float t = sk[j] * c1[j] + ck[j] * s1[j];
                    ck[j] = ck[j] * c1[j] - sk[j] * s1[j];
                    sk[j] = t;
                }
            }
            float o4[4];
#pragma unroll
            for (int j = 0; j < 4; j++) {
                int d = (dmask >> j) & 1;
                float a0 = d ? rB[h] : rA[h];
                float a1 = d ? rC[h] : rB[h];
                float am = a0 * (1.0f - wf[j]) + a1 * wf[j];
                float sig2 = 1.0f + tanh_approx(0.5f * am);
                o4[j] = (sk[j] * cA[h] + ck[j] * cB[h]) * (sig2 * voiced[j]);
            }
            *(float4*)(op + (size_t)h * T_AUD) =
                make_float4(o4[0], o4[1], o4[2], o4[3]);
        }
    }
}

// ---------------- launcher ----------------
extern "C" void kernel_launch(void* const* d_in, const int* in_sizes, int n_in,
                              void* d_out, int out_size)
{
    const float* f0    = (const float*)d_in[0];
    const float* mel   = (const float*)d_in[1];
    const float* noise = (const float*)d_in[2];
    const float* w1    = (const float*)d_in[3];
    const float* b1    = (const float*)d_in[4];
    const float* w2    = (const float*)d_in[5];
    const float* b2    = (const float*)d_in[6];
    const float* als   = (const float*)d_in[7];
    const float* pho   = (const float*)d_in[8];
    const float* lnv   = (const float*)d_in[9];
    const float* lnu   = (const float*)d_in[10];
    float* out = (float*)d_out;

    fused_kernel<<<NBLOCKS, NTHREADS>>>(f0, mel, noise, w1, b1, w2, b2,
                                        als, pho, lnv, lnu, out);
}